// round 2
// baseline (speedup 1.0000x reference)
#include <cuda_runtime.h>
#include <math.h>

#define DIM    4096
#define NH     32
#define HD     128
#define SEQ    4096
#define BATCH  16
#define NSPLIT 4
#define SPLIT_LEN (SEQ / NSPLIT)   // 1024

// ---------------- scratch (no allocs allowed -> __device__ globals) ----------------
// __align__(16): these get float4 views; plain float arrays are only 4B-aligned.
__device__ __align__(16) float g_q[BATCH * DIM];
__device__ __align__(16) float g_k[BATCH * DIM];
__device__ __align__(16) float g_v[BATCH * DIM];
__device__ __align__(16) float g_attn[BATCH * DIM];
__device__ __align__(16) float g_po[BATCH * NH * NSPLIT * HD];   // partial outputs
__device__ float g_pm[BATCH * NH * NSPLIT];        // partial max
__device__ float g_pl[BATCH * NH * NSPLIT];        // partial sum(exp)

// ---------------- projection: each warp computes 2 output columns x 16 batches -----
__device__ __forceinline__ void proj2(const float* __restrict__ X,
                                      const float* __restrict__ W,
                                      int j0, int lane,
                                      float* __restrict__ out) {
    const float4* W0 = reinterpret_cast<const float4*>(W + (size_t)j0 * DIM);
    const float4* W1 = reinterpret_cast<const float4*>(W + (size_t)(j0 + 1) * DIM);
    const float4* X4 = reinterpret_cast<const float4*>(X);

    float a0[BATCH], a1[BATCH];
#pragma unroll
    for (int b = 0; b < BATCH; ++b) { a0[b] = 0.f; a1[b] = 0.f; }

#pragma unroll 2
    for (int it = 0; it < DIM / 128; ++it) {       // 32 iterations
        int idx = it * 32 + lane;                  // float4 index within row
        float4 w0 = W0[idx];
        float4 w1 = W1[idx];
#pragma unroll
        for (int b = 0; b < BATCH; ++b) {
            float4 xv = X4[b * (DIM / 4) + idx];
            a0[b] += w0.x * xv.x + w0.y * xv.y + w0.z * xv.z + w0.w * xv.w;
            a1[b] += w1.x * xv.x + w1.y * xv.y + w1.z * xv.z + w1.w * xv.w;
        }
    }

#pragma unroll
    for (int b = 0; b < BATCH; ++b) {
        float v0 = a0[b], v1 = a1[b];
#pragma unroll
        for (int off = 16; off > 0; off >>= 1) {
            v0 += __shfl_down_sync(0xffffffffu, v0, off);
            v1 += __shfl_down_sync(0xffffffffu, v1, off);
        }
        if (lane == 0) {
            out[b * DIM + j0]     = v0;
            out[b * DIM + j0 + 1] = v1;
        }
    }
}

// grid = 3*DIM/16 = 768 blocks, 256 threads; 16 cols/block (x reused from L1/L2)
__global__ void __launch_bounds__(256) proj_qkv_kernel(const float* __restrict__ x,
                                                       const float* __restrict__ wq,
                                                       const float* __restrict__ wk,
                                                       const float* __restrict__ wv) {
    int warp = threadIdx.x >> 5, lane = threadIdx.x & 31;
    int cg = blockIdx.x * 16 + warp * 2;       // global column 0..12287
    int wsel = cg >> 12;                       // 0=q, 1=k, 2=v
    int j0 = cg & (DIM - 1);
    const float* W = (wsel == 0) ? wq : (wsel == 1) ? wk : wv;
    float* out     = (wsel == 0) ? g_q : (wsel == 1) ? g_k : g_v;
    proj2(x, W, j0, lane, out);
}

// grid = DIM/16 = 256 blocks
__global__ void __launch_bounds__(256) proj_o_kernel(const float* __restrict__ wo,
                                                     float* __restrict__ out) {
    int warp = threadIdx.x >> 5, lane = threadIdx.x & 31;
    int j0 = blockIdx.x * 16 + warp * 2;
    proj2(g_attn, wo, j0, lane, out);
}

// ---------------- flash-decoding split attention ----------------
// grid = (NSPLIT, NH, BATCH), 256 threads
__global__ void __launch_bounds__(256) attn_split_kernel(const float* __restrict__ kc,
                                                         const float* __restrict__ vc) {
    int split = blockIdx.x, h = blockIdx.y, b = blockIdx.z;
    int tid = threadIdx.x, warp = tid >> 5, lane = tid & 31;

    __shared__ float sc[SPLIT_LEN + 1];
    __shared__ __align__(16) float qs[HD];
    __shared__ float redm[8], redl[8];
    __shared__ float osum[HD];

    if (tid < HD) qs[tid] = g_q[b * DIM + h * HD + tid];
    __syncthreads();

    const float scale = 0.08838834764831845f;   // 1/sqrt(128)
    const bool last = (split == NSPLIT - 1);
    const size_t base = (((size_t)b * NH + h) * SEQ + (size_t)split * SPLIT_LEN) * HD;

    float4 q4 = *reinterpret_cast<const float4*>(&qs[lane * 4]);

    // Phase 1: scores. One warp per row; each lane handles 4 of 128 dims.
#pragma unroll 4
    for (int s = warp; s < SPLIT_LEN; s += 8) {
        float4 k4 = *reinterpret_cast<const float4*>(kc + base + (size_t)s * HD + lane * 4);
        float v = q4.x * k4.x + q4.y * k4.y + q4.z * k4.z + q4.w * k4.w;
#pragma unroll
        for (int off = 16; off > 0; off >>= 1) v += __shfl_down_sync(0xffffffffu, v, off);
        if (lane == 0) sc[s] = v * scale;
    }
    if (last && warp == 0) {   // appended new token from k projection
        float4 k4 = *reinterpret_cast<const float4*>(g_k + b * DIM + h * HD + lane * 4);
        float v = q4.x * k4.x + q4.y * k4.y + q4.z * k4.z + q4.w * k4.w;
#pragma unroll
        for (int off = 16; off > 0; off >>= 1) v += __shfl_down_sync(0xffffffffu, v, off);
        if (lane == 0) sc[SPLIT_LEN] = v * scale;
    }
    __syncthreads();

    // Phase 2: partial softmax (max then exp-sum)
    int ns = SPLIT_LEN + (last ? 1 : 0);
    float m = -1e30f;
    for (int s = tid; s < ns; s += 256) m = fmaxf(m, sc[s]);
#pragma unroll
    for (int off = 16; off > 0; off >>= 1) m = fmaxf(m, __shfl_xor_sync(0xffffffffu, m, off));
    if (lane == 0) redm[warp] = m;
    __syncthreads();
    float M = redm[0];
#pragma unroll
    for (int w = 1; w < 8; ++w) M = fmaxf(M, redm[w]);

    float lsum = 0.f;
    for (int s = tid; s < ns; s += 256) {
        float p = __expf(sc[s] - M);
        sc[s] = p;
        lsum += p;
    }
#pragma unroll
    for (int off = 16; off > 0; off >>= 1) lsum += __shfl_xor_sync(0xffffffffu, lsum, off);
    if (lane == 0) redl[warp] = lsum;
    __syncthreads();   // also orders sc[] writes before phase 3 reads

    // Phase 3: o[d] = sum_s p[s] * V[s][d]. 2 rows in flight (tid>>7), coalesced over d.
    int d = tid & (HD - 1);
    int sh = tid >> 7;
    const float* Vp = vc + base + d;
    float acc = 0.f;
#pragma unroll 8
    for (int s = sh; s < SPLIT_LEN; s += 2)
        acc += sc[s] * Vp[(size_t)s * HD];

    if (sh == 1) osum[d] = acc;
    __syncthreads();
    int pi = (b * NH + h) * NSPLIT + split;
    if (sh == 0) {
        float tot = acc + osum[d];
        if (last) tot += sc[SPLIT_LEN] * g_v[b * DIM + h * HD + d];
        g_po[pi * HD + d] = tot;
    }
    if (tid == 0) {
        float L = 0.f;
#pragma unroll
        for (int w = 0; w < 8; ++w) L += redl[w];
        g_pm[pi] = M;
        g_pl[pi] = L;
    }
}

// grid = BATCH*NH = 512 blocks, 128 threads
__global__ void __launch_bounds__(128) attn_combine_kernel() {
    int bh = blockIdx.x;
    int d = threadIdx.x;
    int b = bh >> 5, h = bh & 31;

    float ms[NSPLIT];
    float M = -1e30f;
#pragma unroll
    for (int i = 0; i < NSPLIT; ++i) { ms[i] = g_pm[bh * NSPLIT + i]; M = fmaxf(M, ms[i]); }
    float L = 0.f, w[NSPLIT];
#pragma unroll
    for (int i = 0; i < NSPLIT; ++i) { w[i] = __expf(ms[i] - M); L += g_pl[bh * NSPLIT + i] * w[i]; }
    float o = 0.f;
#pragma unroll
    for (int i = 0; i < NSPLIT; ++i) o += g_po[(bh * NSPLIT + i) * HD + d] * w[i];
    g_attn[b * DIM + h * HD + d] = o / L;
}

// ---------------- launch ----------------
extern "C" void kernel_launch(void* const* d_in, const int* in_sizes, int n_in,
                              void* d_out, int out_size) {
    const float* x  = (const float*)d_in[0];
    const float* kc = (const float*)d_in[1];
    const float* vc = (const float*)d_in[2];
    const float* wq = (const float*)d_in[3];
    const float* wk = (const float*)d_in[4];
    const float* wv = (const float*)d_in[5];
    const float* wo = (const float*)d_in[6];
    float* out = (float*)d_out;

    proj_qkv_kernel<<<3 * DIM / 16, 256>>>(x, wq, wk, wv);
    attn_split_kernel<<<dim3(NSPLIT, NH, BATCH), 256>>>(kc, vc);
    attn_combine_kernel<<<BATCH * NH, 128>>>();
    proj_o_kernel<<<DIM / 16, 256>>>(wo, out);
}